// round 15
// baseline (speedup 1.0000x reference)
#include <cuda_runtime.h>
#include <cuda_fp16.h>
#include <cuda_bf16.h>
#include <stdint.h>

#define BB   64
#define NN   4096
#define EE   4096
#define CNNZ 32768
#define CC   256
#define MTOT (BB * NN)  // 262144 rows

// ---------------- device scratch (no allocs allowed) ----------------
__device__ __half g_hA[(size_t)MTOT * CC];    // 134 MB
__device__ __half g_hB[(size_t)MTOT * CC];    // 134 MB
__device__ float  g_v[CC];                    // b1 @ W2
__device__ uint4  g_Wpk[16384];               // packed W12 frags: [s16][t32][lane32]
__device__ int    g_rowptrD[EE + 1], g_rowptrS[NN + 1];
__device__ int    g_colD[CNNZ], g_colS[CNNZ];
__device__ int    g_deg[EE + NN];             // [0,EE): D (edges), [EE,EE+NN): S (nodes)
__device__ int    g_curD[EE], g_curS[NN];
__device__ float  g_Binv[EE], g_Dinv[NN];

// ---------------- helpers ----------------
__device__ __forceinline__ unsigned bf2u(__nv_bfloat162 h) {
    return *reinterpret_cast<unsigned*>(&h);
}

// split a float pair into (hi bf16x2, lo bf16x2): x + residual
__device__ __forceinline__ void split2(float x, float y, unsigned& hi, unsigned& lo) {
    __nv_bfloat162 h = __floats2bfloat162_rn(x, y);
    float rx = x - __low2float(h);
    float ry = y - __high2float(h);
    __nv_bfloat162 l = __floats2bfloat162_rn(rx, ry);
    hi = bf2u(h);
    lo = bf2u(l);
}

__device__ __forceinline__ void mma16816(float* d, const unsigned* a, const unsigned* b) {
    asm volatile(
        "mma.sync.aligned.m16n8k16.row.col.f32.bf16.bf16.f32 "
        "{%0,%1,%2,%3}, {%4,%5,%6,%7}, {%8,%9}, {%0,%1,%2,%3};\n"
        : "+f"(d[0]), "+f"(d[1]), "+f"(d[2]), "+f"(d[3])
        : "r"(a[0]), "r"(a[1]), "r"(a[2]), "r"(a[3]), "r"(b[0]), "r"(b[1]));
}

__device__ __forceinline__ void acc8(float* a, const uint4& v) {
    float2 f0 = __half22float2(*(const __half2*)&v.x);
    float2 f1 = __half22float2(*(const __half2*)&v.y);
    float2 f2 = __half22float2(*(const __half2*)&v.z);
    float2 f3 = __half22float2(*(const __half2*)&v.w);
    a[0] += f0.x; a[1] += f0.y; a[2] += f1.x; a[3] += f1.y;
    a[4] += f2.x; a[5] += f2.y; a[6] += f3.x; a[7] += f3.y;
}

__device__ __forceinline__ uint4 pack_h8(const float* a, float sc) {
    uint4 o;
    *(__half2*)&o.x = __floats2half2_rn(a[0] * sc, a[1] * sc);
    *(__half2*)&o.y = __floats2half2_rn(a[2] * sc, a[3] * sc);
    *(__half2*)&o.z = __floats2half2_rn(a[4] * sc, a[5] * sc);
    *(__half2*)&o.w = __floats2half2_rn(a[6] * sc, a[7] * sc);
    return o;
}

// ---------------- CSR build (degrees zeroed by one cudaMemsetAsync) ----------------
__global__ void count_kernel(const int* __restrict__ src, const int* __restrict__ dst) {
    int j = blockIdx.x * blockDim.x + threadIdx.x;  // CNNZ
    atomicAdd(&g_deg[EE + src[j]], 1);  // S (node degree)
    atomicAdd(&g_deg[dst[j]], 1);       // D (hyperedge size)
}

__global__ void scan_kernel() {
    __shared__ int sh[1024];
    int which = blockIdx.x;  // 0: D (edges), 1: S (nodes)
    const int* deg = which ? (g_deg + EE) : g_deg;
    int* rowptr    = which ? g_rowptrS : g_rowptrD;
    int* cur       = which ? g_curS : g_curD;
    float* inv     = which ? g_Dinv : g_Binv;
    int t = threadIdx.x;
    int d0 = deg[4*t], d1 = deg[4*t+1], d2 = deg[4*t+2], d3 = deg[4*t+3];
    int s = d0 + d1 + d2 + d3;
    sh[t] = s;
    __syncthreads();
    for (int off = 1; off < 1024; off <<= 1) {
        int v = (t >= off) ? sh[t - off] : 0;
        __syncthreads();
        sh[t] += v;
        __syncthreads();
    }
    int excl = sh[t] - s;
    int p0 = excl, p1 = excl + d0, p2 = p1 + d1, p3 = p2 + d2;
    rowptr[4*t] = p0; rowptr[4*t+1] = p1; rowptr[4*t+2] = p2; rowptr[4*t+3] = p3;
    cur[4*t] = p0; cur[4*t+1] = p1; cur[4*t+2] = p2; cur[4*t+3] = p3;
    inv[4*t]   = d0 ? 1.0f / d0 : 0.0f;
    inv[4*t+1] = d1 ? 1.0f / d1 : 0.0f;
    inv[4*t+2] = d2 ? 1.0f / d2 : 0.0f;
    inv[4*t+3] = d3 ? 1.0f / d3 : 0.0f;
    if (t == 1023) rowptr[4096] = sh[1023];
}

__global__ void fill_kernel(const int* __restrict__ src, const int* __restrict__ dst) {
    int j = blockIdx.x * blockDim.x + threadIdx.x;  // CNNZ
    int e = dst[j], n = src[j];
    g_colD[atomicAdd(&g_curD[e], 1)] = n;
    g_colS[atomicAdd(&g_curS[n], 1)] = e;
}

// ---------------- fused dense prep: W12 pack (and v = b1 @ W2) ----------------
__global__ void prep_w_kernel(const float* __restrict__ W1, const float* __restrict__ b1,
                              const float* __restrict__ W2) {
    if (blockIdx.x == 64) {
        int c = threadIdx.x;
        float s = 0.f;
        for (int d = 0; d < CC; d++) s += b1[d] * W2[d * CC + c];
        g_v[c] = s;
        return;
    }
    int i = blockIdx.x * blockDim.x + threadIdx.x;  // 16384
    int l = i & 31, t = (i >> 5) & 31, s = i >> 10;
    int lr = l >> 2, lc = l & 3;
    int n = t * 8 + lr;
    int k0 = s * 16 + 2 * lc;
    float w00 = 0.f, w01 = 0.f, w10 = 0.f, w11 = 0.f;
    for (int d = 0; d < CC; d++) {
        float w2 = W2[d * CC + n];
        w00 += W1[k0 * CC + d] * w2;
        w01 += W1[(k0 + 1) * CC + d] * w2;
        w10 += W1[(k0 + 8) * CC + d] * w2;
        w11 += W1[(k0 + 9) * CC + d] * w2;
    }
    unsigned b0h, b0l, b1h, b1l;
    split2(w00, w01, b0h, b0l);
    split2(w10, w11, b1h, b1l);
    g_Wpk[i] = make_uint4(b0h, b1h, b0l, b1l);
}

// ---------------- GEMM: Yh[M,256] = X[M,256] @ W12 (fp16 output) ----------------
// Round-11 champion config: 256 thr = 8 warps (2 M x 4 N); tile M=64, N=256.
__global__ void __launch_bounds__(256, 2) gemm_kernel(const float* __restrict__ X,
                                                      __half* __restrict__ Y) {
    __shared__ uint4 sW[2][32][32];  // [kstep][ntile][lane], 32 KB
    int tid = threadIdx.x;
    int w = tid >> 5, l = tid & 31;
    int wm = w >> 2, wn = w & 3;
    int lr = l >> 2, lc = l & 3;
    int mbase = blockIdx.x * 64 + wm * 32;
    const float* xb = X + (size_t)mbase * CC;

    float acc[2][8][4];
#pragma unroll
    for (int mf = 0; mf < 2; mf++)
#pragma unroll
        for (int nf = 0; nf < 8; nf++)
#pragma unroll
            for (int q = 0; q < 4; q++) acc[mf][nf][q] = 0.f;

    for (int ch = 0; ch < 8; ch++) {
        __syncthreads();
        {
            const uint4* src = g_Wpk + ch * 2048;
            uint4* dst = &sW[0][0][0];
            for (int i = tid; i < 2048; i += 256) dst[i] = src[i];
        }
        __syncthreads();
#pragma unroll
        for (int ks = 0; ks < 2; ks++) {
            int k0 = ch * 32 + ks * 16;
            unsigned ah[2][4], al[2][4];
#pragma unroll
            for (int mf = 0; mf < 2; mf++) {
                const float* xr = xb + (size_t)(mf * 16 + lr) * CC + k0 + 2 * lc;
                float2 p0 = *(const float2*)(xr);
                float2 p1 = *(const float2*)(xr + 8 * CC);
                float2 p2 = *(const float2*)(xr + 8);
                float2 p3 = *(const float2*)(xr + 8 * CC + 8);
                split2(p0.x, p0.y, ah[mf][0], al[mf][0]);
                split2(p1.x, p1.y, ah[mf][1], al[mf][1]);
                split2(p2.x, p2.y, ah[mf][2], al[mf][2]);
                split2(p3.x, p3.y, ah[mf][3], al[mf][3]);
            }
#pragma unroll
            for (int nf = 0; nf < 8; nf++) {
                uint4 wf = sW[ks][wn * 8 + nf][l];
                unsigned bh[2] = {wf.x, wf.y};
                unsigned bl[2] = {wf.z, wf.w};
#pragma unroll
                for (int mf = 0; mf < 2; mf++) {
                    mma16816(acc[mf][nf], ah[mf], bh);  // hi*hi
                    mma16816(acc[mf][nf], al[mf], bh);  // lo*hi
                    mma16816(acc[mf][nf], ah[mf], bl);  // hi*lo
                }
            }
        }
    }
    // epilogue: fp32 acc -> fp16 store
#pragma unroll
    for (int mf = 0; mf < 2; mf++)
#pragma unroll
        for (int nf = 0; nf < 8; nf++) {
            size_t row0 = (size_t)mbase + mf * 16 + lr;
            int col = wn * 64 + nf * 8 + 2 * lc;
            *(__half2*)(Y + row0 * CC + col) =
                __floats2half2_rn(acc[mf][nf][0], acc[mf][nf][1]);
            *(__half2*)(Y + (row0 + 8) * CC + col) =
                __floats2half2_rn(acc[mf][nf][2], acc[mf][nf][3]);
        }
}

// ---------------- fused double-hop kernel ----------------
// One CTA = one (8-channel slice, batch). Does node->edge->node entirely in smem:
//   phase 0: load node slice In[b, :, ch0:ch0+8] (fp16) into sIn        (64 KB)
//   phase 1: edge[e] = Binv[e] * sum_{n in D-row e} sIn[n]   -> sEdge (fp16, 64 KB)
//   phase 2: node[n] = Dinv[n] * sum_{e in S-row n} sEdge[e] -> gmem
// final_mode: write fp32 + uu*g_v + b2 to d_out instead of fp16.
// Rounding points and summation order identical to the unfused 2-kernel chain.
__global__ void __launch_bounds__(512) fused_hop_kernel(
    const __half* __restrict__ In, void* __restrict__ Out,
    const float* __restrict__ b2, int final_mode) {
    extern __shared__ uint4 sm[];
    uint4* sIn = sm;          // [4096] = node slice
    uint4* sEdge = sm + NN;   // [4096] = edge intermediate
    int tid = threadIdx.x;
    int c4 = blockIdx.x;      // uint4-slice (8 channels), 0..31
    int b  = blockIdx.y;

    // phase 0: load node slice
    const uint4* In4 = (const uint4*)In;
    size_t inbase = (size_t)b * NN * 32 + c4;
#pragma unroll
    for (int n = tid; n < NN; n += 512)
        sIn[n] = In4[inbase + (size_t)n * 32];
    __syncthreads();

    // phase 1: node -> edge (CSR D, scale Binv)
    for (int e = tid; e < EE; e += 512) {
        int s = g_rowptrD[e], t = g_rowptrD[e + 1];
        float a[8] = {0, 0, 0, 0, 0, 0, 0, 0};
        for (int j = s; j < t; j++) acc8(a, sIn[g_colD[j]]);
        sEdge[e] = pack_h8(a, g_Binv[e]);
    }
    __syncthreads();

    // phase 2: edge -> node (CSR S, scale Dinv), write out
    if (!final_mode) {
        uint4* Out4 = (uint4*)Out;
        for (int n = tid; n < NN; n += 512) {
            int s = g_rowptrS[n], t = g_rowptrS[n + 1];
            float a[8] = {0, 0, 0, 0, 0, 0, 0, 0};
            for (int j = s; j < t; j++) acc8(a, sEdge[g_colS[j]]);
            Out4[inbase + (size_t)n * 32] = pack_h8(a, g_Dinv[n]);
        }
    } else {
        int ch0 = c4 * 8;
        float4 vv0 = *(const float4*)(g_v + ch0);
        float4 vv1 = *(const float4*)(g_v + ch0 + 4);
        float4 bb0 = *(const float4*)(b2 + ch0);
        float4 bb1 = *(const float4*)(b2 + ch0 + 4);
        for (int n = tid; n < NN; n += 512) {
            int s = g_rowptrS[n], t = g_rowptrS[n + 1];
            float a[8] = {0, 0, 0, 0, 0, 0, 0, 0};
            for (int j = s; j < t; j++) acc8(a, sEdge[g_colS[j]]);
            float sc = g_Dinv[n];
            float uu = (sc > 0.f) ? 1.f : 0.f;
            float* p = (float*)Out + ((size_t)b * NN + n) * CC + ch0;
            *(float4*)(p)     = make_float4(a[0] * sc + uu * vv0.x + bb0.x,
                                            a[1] * sc + uu * vv0.y + bb0.y,
                                            a[2] * sc + uu * vv0.z + bb0.z,
                                            a[3] * sc + uu * vv0.w + bb0.w);
            *(float4*)(p + 4) = make_float4(a[4] * sc + uu * vv1.x + bb1.x,
                                            a[5] * sc + uu * vv1.y + bb1.y,
                                            a[6] * sc + uu * vv1.z + bb1.z,
                                            a[7] * sc + uu * vv1.w + bb1.w);
        }
    }
}

// ---------------- launch ----------------
extern "C" void kernel_launch(void* const* d_in, const int* in_sizes, int n_in,
                              void* d_out, int out_size) {
    (void)in_sizes; (void)n_in; (void)out_size;
    const float* x   = (const float*)d_in[0];
    const int*   hei = (const int*)d_in[1];
    const float* W1  = (const float*)d_in[2];
    const float* b1  = (const float*)d_in[3];
    const float* W2  = (const float*)d_in[4];
    const float* b2  = (const float*)d_in[5];
    float* out = (float*)d_out;
    const int* src = hei;
    const int* dst = hei + CNNZ;

    void *pA = nullptr, *pB = nullptr, *pDeg = nullptr;
    cudaGetSymbolAddress(&pA, g_hA);
    cudaGetSymbolAddress(&pB, g_hB);
    cudaGetSymbolAddress(&pDeg, g_deg);
    __half* hA = (__half*)pA;
    __half* hB = (__half*)pB;

    static int smem_set = 0;
    if (!smem_set) {
        cudaFuncSetAttribute(fused_hop_kernel,
                             cudaFuncAttributeMaxDynamicSharedMemorySize, 2 * NN * 16);
        smem_set = 1;
    }

    cudaMemsetAsync(pDeg, 0, (EE + NN) * sizeof(int));
    count_kernel<<<64, 512>>>(src, dst);
    scan_kernel<<<2, 1024>>>();
    fill_kernel<<<64, 512>>>(src, dst);
    prep_w_kernel<<<65, 256>>>(W1, b1, W2);
    gemm_kernel<<<MTOT / 64, 256>>>(x, hA);

    // two fused double-hops (node->edge->node each), smem-resident intermediate
    dim3 fg(32, BB);
    fused_hop_kernel<<<fg, 512, 2 * NN * 16>>>(hA, hB, nullptr, 0);
    fused_hop_kernel<<<fg, 512, 2 * NN * 16>>>(hB, out, b2, 1);
}

// round 17
// speedup vs baseline: 2.2351x; 2.2351x over previous
#include <cuda_runtime.h>
#include <cuda_fp16.h>
#include <cuda_bf16.h>
#include <stdint.h>

#define BB   64
#define NN   4096
#define EE   4096
#define CNNZ 32768
#define CC   256
#define MTOT (BB * NN)  // 262144 rows
#define SLAB ((size_t)NN * (CC / 8))  // uint4s per batch slab = 131072

// ---------------- device scratch (no allocs allowed) ----------------
__device__ __half g_hA[(size_t)MTOT * CC];    // 134 MB
__device__ __half g_hB[(size_t)MTOT * CC];    // 134 MB
__device__ float  g_v[CC];                    // b1 @ W2
__device__ uint2  g_Wpk[16384];               // packed fp16 W12 frags: [s16][t32][lane32]
__device__ int    g_rowptrD[EE + 1], g_rowptrS[NN + 1];
__device__ int    g_colD[CNNZ], g_colS[CNNZ];
__device__ int    g_deg[EE + NN];             // [0,EE): D (edges), [EE,EE+NN): S (nodes)
__device__ int    g_curD[EE], g_curS[NN];
__device__ float  g_Binv[EE], g_Dinv[NN];

// ---------------- helpers ----------------
__device__ __forceinline__ unsigned h2u(__half2 h) {
    return *reinterpret_cast<unsigned*>(&h);
}

__device__ __forceinline__ void mma16816h(float* d, const unsigned* a, const unsigned* b) {
    asm volatile(
        "mma.sync.aligned.m16n8k16.row.col.f32.f16.f16.f32 "
        "{%0,%1,%2,%3}, {%4,%5,%6,%7}, {%8,%9}, {%0,%1,%2,%3};\n"
        : "+f"(d[0]), "+f"(d[1]), "+f"(d[2]), "+f"(d[3])
        : "r"(a[0]), "r"(a[1]), "r"(a[2]), "r"(a[3]), "r"(b[0]), "r"(b[1]));
}

__device__ __forceinline__ void acc8(float* a, const uint4& v) {
    float2 f0 = __half22float2(*(const __half2*)&v.x);
    float2 f1 = __half22float2(*(const __half2*)&v.y);
    float2 f2 = __half22float2(*(const __half2*)&v.z);
    float2 f3 = __half22float2(*(const __half2*)&v.w);
    a[0] += f0.x; a[1] += f0.y; a[2] += f1.x; a[3] += f1.y;
    a[4] += f2.x; a[5] += f2.y; a[6] += f3.x; a[7] += f3.y;
}

__device__ __forceinline__ uint4 pack_h8(const float* a, float sc) {
    uint4 o;
    *(__half2*)&o.x = __floats2half2_rn(a[0] * sc, a[1] * sc);
    *(__half2*)&o.y = __floats2half2_rn(a[2] * sc, a[3] * sc);
    *(__half2*)&o.z = __floats2half2_rn(a[4] * sc, a[5] * sc);
    *(__half2*)&o.w = __floats2half2_rn(a[6] * sc, a[7] * sc);
    return o;
}

// ---------------- CSR build (degrees zeroed by one cudaMemsetAsync) ----------------
__global__ void count_kernel(const int* __restrict__ src, const int* __restrict__ dst) {
    int j = blockIdx.x * blockDim.x + threadIdx.x;  // CNNZ
    atomicAdd(&g_deg[EE + src[j]], 1);  // S (node degree)
    atomicAdd(&g_deg[dst[j]], 1);       // D (hyperedge size)
}

__global__ void scan_kernel() {
    __shared__ int sh[1024];
    int which = blockIdx.x;  // 0: D (edges), 1: S (nodes)
    const int* deg = which ? (g_deg + EE) : g_deg;
    int* rowptr    = which ? g_rowptrS : g_rowptrD;
    int* cur       = which ? g_curS : g_curD;
    float* inv     = which ? g_Dinv : g_Binv;
    int t = threadIdx.x;
    int d0 = deg[4*t], d1 = deg[4*t+1], d2 = deg[4*t+2], d3 = deg[4*t+3];
    int s = d0 + d1 + d2 + d3;
    sh[t] = s;
    __syncthreads();
    for (int off = 1; off < 1024; off <<= 1) {
        int v = (t >= off) ? sh[t - off] : 0;
        __syncthreads();
        sh[t] += v;
        __syncthreads();
    }
    int excl = sh[t] - s;
    int p0 = excl, p1 = excl + d0, p2 = p1 + d1, p3 = p2 + d2;
    rowptr[4*t] = p0; rowptr[4*t+1] = p1; rowptr[4*t+2] = p2; rowptr[4*t+3] = p3;
    cur[4*t] = p0; cur[4*t+1] = p1; cur[4*t+2] = p2; cur[4*t+3] = p3;
    inv[4*t]   = d0 ? 1.0f / d0 : 0.0f;
    inv[4*t+1] = d1 ? 1.0f / d1 : 0.0f;
    inv[4*t+2] = d2 ? 1.0f / d2 : 0.0f;
    inv[4*t+3] = d3 ? 1.0f / d3 : 0.0f;
    if (t == 1023) rowptr[4096] = sh[1023];
}

__global__ void fill_kernel(const int* __restrict__ src, const int* __restrict__ dst) {
    int j = blockIdx.x * blockDim.x + threadIdx.x;  // CNNZ
    int e = dst[j], n = src[j];
    g_colD[atomicAdd(&g_curD[e], 1)] = n;
    g_colS[atomicAdd(&g_curS[n], 1)] = e;
}

// ---------------- fused dense prep: W12 pack fp16 (and v = b1 @ W2) ----------------
__global__ void prep_w_kernel(const float* __restrict__ W1, const float* __restrict__ b1,
                              const float* __restrict__ W2) {
    if (blockIdx.x == 64) {
        int c = threadIdx.x;
        float s = 0.f;
        for (int d = 0; d < CC; d++) s += b1[d] * W2[d * CC + c];
        g_v[c] = s;
        return;
    }
    int i = blockIdx.x * blockDim.x + threadIdx.x;  // 16384
    int l = i & 31, t = (i >> 5) & 31, s = i >> 10;
    int lr = l >> 2, lc = l & 3;
    int n = t * 8 + lr;
    int k0 = s * 16 + 2 * lc;
    float w00 = 0.f, w01 = 0.f, w10 = 0.f, w11 = 0.f;
    for (int d = 0; d < CC; d++) {
        float w2 = W2[d * CC + n];
        w00 += W1[k0 * CC + d] * w2;
        w01 += W1[(k0 + 1) * CC + d] * w2;
        w10 += W1[(k0 + 8) * CC + d] * w2;
        w11 += W1[(k0 + 9) * CC + d] * w2;
    }
    g_Wpk[i] = make_uint2(h2u(__floats2half2_rn(w00, w01)),
                          h2u(__floats2half2_rn(w10, w11)));
}

// ---------------- GEMM: Yh[M,256] = X[M,256] @ W12 (fp16 in/out, single product) ----
// 256 thr = 8 warps (2 M x 4 N); tile M=64, N=256; warp tile 32x64.
__global__ void __launch_bounds__(256, 2) gemm_kernel(const float* __restrict__ X,
                                                      __half* __restrict__ Y) {
    __shared__ uint2 sW[2][32][32];  // [kstep][ntile][lane], 16 KB
    int tid = threadIdx.x;
    int w = tid >> 5, l = tid & 31;
    int wm = w >> 2, wn = w & 3;
    int lr = l >> 2, lc = l & 3;
    int mbase = blockIdx.x * 64 + wm * 32;
    const float* xb = X + (size_t)mbase * CC;

    float acc[2][8][4];
#pragma unroll
    for (int mf = 0; mf < 2; mf++)
#pragma unroll
        for (int nf = 0; nf < 8; nf++)
#pragma unroll
            for (int q = 0; q < 4; q++) acc[mf][nf][q] = 0.f;

    for (int ch = 0; ch < 8; ch++) {
        __syncthreads();
        {
            const uint2* src = g_Wpk + ch * 2048;
            uint2* dst = &sW[0][0][0];
            for (int i = tid; i < 2048; i += 256) dst[i] = src[i];
        }
        __syncthreads();
#pragma unroll
        for (int ks = 0; ks < 2; ks++) {
            int k0 = ch * 32 + ks * 16;
            unsigned ah[2][4];
#pragma unroll
            for (int mf = 0; mf < 2; mf++) {
                const float* xr = xb + (size_t)(mf * 16 + lr) * CC + k0 + 2 * lc;
                float2 p0 = *(const float2*)(xr);
                float2 p1 = *(const float2*)(xr + 8 * CC);
                float2 p2 = *(const float2*)(xr + 8);
                float2 p3 = *(const float2*)(xr + 8 * CC + 8);
                ah[mf][0] = h2u(__floats2half2_rn(p0.x, p0.y));
                ah[mf][1] = h2u(__floats2half2_rn(p1.x, p1.y));
                ah[mf][2] = h2u(__floats2half2_rn(p2.x, p2.y));
                ah[mf][3] = h2u(__floats2half2_rn(p3.x, p3.y));
            }
#pragma unroll
            for (int nf = 0; nf < 8; nf++) {
                uint2 wf = sW[ks][wn * 8 + nf][l];
                unsigned bh[2] = {wf.x, wf.y};
#pragma unroll
                for (int mf = 0; mf < 2; mf++)
                    mma16816h(acc[mf][nf], ah[mf], bh);
            }
        }
    }
    // epilogue: fp32 acc -> fp16 store
#pragma unroll
    for (int mf = 0; mf < 2; mf++)
#pragma unroll
        for (int nf = 0; nf < 8; nf++) {
            size_t row0 = (size_t)mbase + mf * 16 + lr;
            int col = wn * 64 + nf * 8 + 2 * lc;
            *(__half2*)(Y + row0 * CC + col) =
                __floats2half2_rn(acc[mf][nf][0], acc[mf][nf][1]);
            *(__half2*)(Y + (row0 + 8) * CC + col) =
                __floats2half2_rn(acc[mf][nf][2], acc[mf][nf][3]);
        }
}

// ---------------- CSR gather-sum hop (fp16 in/out), quad-batch (MLP=4) ----------------
// For batches b0..b0+3:  Out[b,r,:] = inv[r] * sum_{j in row r} In[b, cols[j], :]
__global__ void __launch_bounds__(256) gather_h_kernel(
    const __half* __restrict__ In, __half* __restrict__ Out, int use_dst) {
    int r = blockIdx.x * blockDim.y + threadIdx.y;
    int b0 = blockIdx.y * 4;
    int lane = threadIdx.x;  // 0..31
    const int* __restrict__ rowptr = use_dst ? g_rowptrD : g_rowptrS;
    const int* __restrict__ cols   = use_dst ? g_colD : g_colS;
    const float* __restrict__ inv  = use_dst ? g_Binv : g_Dinv;
    const uint4* __restrict__ base = (const uint4*)In + (size_t)b0 * SLAB;
    int s = rowptr[r], e = rowptr[r + 1];
    float a0[8] = {0,0,0,0,0,0,0,0};
    float a1[8] = {0,0,0,0,0,0,0,0};
    float a2[8] = {0,0,0,0,0,0,0,0};
    float a3[8] = {0,0,0,0,0,0,0,0};
    for (int j = s; j < e; j++) {
        size_t off = (size_t)cols[j] * 32 + lane;
        uint4 v0 = base[off];
        uint4 v1 = base[off + SLAB];
        uint4 v2 = base[off + 2 * SLAB];
        uint4 v3 = base[off + 3 * SLAB];
        acc8(a0, v0); acc8(a1, v1); acc8(a2, v2); acc8(a3, v3);
    }
    float sc = inv[r];
    size_t orow = ((size_t)b0 * NN + r) * 32 + lane;
    ((uint4*)Out)[orow]                       = pack_h8(a0, sc);
    ((uint4*)Out)[orow + NN * 32]             = pack_h8(a1, sc);
    ((uint4*)Out)[orow + 2 * (size_t)NN * 32] = pack_h8(a2, sc);
    ((uint4*)Out)[orow + 3 * (size_t)NN * 32] = pack_h8(a3, sc);
}

// ---------------- final hop: fp16 in, fp32 out, + u*v + b2, quad-batch ----------------
__global__ void __launch_bounds__(256) gather_final_kernel(
    const __half* __restrict__ In, float* __restrict__ Out,
    const float* __restrict__ b2) {
    int r = blockIdx.x * blockDim.y + threadIdx.y;
    int b0 = blockIdx.y * 4;
    int lane = threadIdx.x;  // 0..31, 8 channels each
    const uint4* __restrict__ base = (const uint4*)In + (size_t)b0 * SLAB;
    int s = g_rowptrS[r], e = g_rowptrS[r + 1];
    float a0[8] = {0,0,0,0,0,0,0,0};
    float a1[8] = {0,0,0,0,0,0,0,0};
    float a2[8] = {0,0,0,0,0,0,0,0};
    float a3[8] = {0,0,0,0,0,0,0,0};
    for (int j = s; j < e; j++) {
        size_t off = (size_t)g_colS[j] * 32 + lane;
        uint4 v0 = base[off];
        uint4 v1 = base[off + SLAB];
        uint4 v2 = base[off + 2 * SLAB];
        uint4 v3 = base[off + 3 * SLAB];
        acc8(a0, v0); acc8(a1, v1); acc8(a2, v2); acc8(a3, v3);
    }
    float sc = g_Dinv[r];
    float uu = (sc > 0.f) ? 1.f : 0.f;  // (P*1)[r]
    float add[8];
    {
        float4 v0 = ((const float4*)g_v)[lane * 2];
        float4 v1 = ((const float4*)g_v)[lane * 2 + 1];
        float4 c0 = ((const float4*)b2)[lane * 2];
        float4 c1 = ((const float4*)b2)[lane * 2 + 1];
        add[0] = uu * v0.x + c0.x; add[1] = uu * v0.y + c0.y;
        add[2] = uu * v0.z + c0.z; add[3] = uu * v0.w + c0.w;
        add[4] = uu * v1.x + c1.x; add[5] = uu * v1.y + c1.y;
        add[6] = uu * v1.z + c1.z; add[7] = uu * v1.w + c1.w;
    }
    float* orow = Out + ((size_t)b0 * NN + r) * CC + lane * 8;
#pragma unroll
    for (int k = 0; k < 4; k++) {
        const float* a = (k == 0) ? a0 : (k == 1) ? a1 : (k == 2) ? a2 : a3;
        float* p = orow + (size_t)k * NN * CC;
        *(float4*)(p)     = make_float4(a[0] * sc + add[0], a[1] * sc + add[1],
                                        a[2] * sc + add[2], a[3] * sc + add[3]);
        *(float4*)(p + 4) = make_float4(a[4] * sc + add[4], a[5] * sc + add[5],
                                        a[6] * sc + add[6], a[7] * sc + add[7]);
    }
}

// ---------------- launch ----------------
extern "C" void kernel_launch(void* const* d_in, const int* in_sizes, int n_in,
                              void* d_out, int out_size) {
    (void)in_sizes; (void)n_in; (void)out_size;
    const float* x   = (const float*)d_in[0];
    const int*   hei = (const int*)d_in[1];
    const float* W1  = (const float*)d_in[2];
    const float* b1  = (const float*)d_in[3];
    const float* W2  = (const float*)d_in[4];
    const float* b2  = (const float*)d_in[5];
    float* out = (float*)d_out;
    const int* src = hei;
    const int* dst = hei + CNNZ;

    void *pA = nullptr, *pB = nullptr, *pDeg = nullptr;
    cudaGetSymbolAddress(&pA, g_hA);
    cudaGetSymbolAddress(&pB, g_hB);
    cudaGetSymbolAddress(&pDeg, g_deg);
    __half* hA = (__half*)pA;
    __half* hB = (__half*)pB;

    cudaMemsetAsync(pDeg, 0, (EE + NN) * sizeof(int));
    count_kernel<<<64, 512>>>(src, dst);
    scan_kernel<<<2, 1024>>>();
    fill_kernel<<<64, 512>>>(src, dst);
    prep_w_kernel<<<65, 256>>>(W1, b1, W2);
    gemm_kernel<<<MTOT / 64, 256>>>(x, hA);

    // 4 propagation hops: D, S, D, S(+bias); fp16 intermediates, quad-batch
    dim3 gb(NN / 8, BB / 4), tb(32, 8);
    gather_h_kernel<<<gb, tb>>>(hA, hB, 1);       // node -> edge (Binv)
    gather_h_kernel<<<gb, tb>>>(hB, hA, 0);       // edge -> node (Dinv)
    gather_h_kernel<<<gb, tb>>>(hA, hB, 1);       // node -> edge (Binv)
    gather_final_kernel<<<gb, tb>>>(hB, out, b2); // edge -> node + u*v + b2 (fp32)
}